// round 1
// baseline (speedup 1.0000x reference)
#include <cuda_runtime.h>
#include <cstdint>

#define BATCH 8192
#define NNEI  32
#define DIN   512
#define DHID  512
#define DOUT  512

// Scratch for pooled activations [BATCH, DHID] (device global: no allocs allowed)
__device__ float g_pooled[BATCH * DHID];

__device__ __forceinline__ uint32_t f2tf(float x) {
    uint32_t r;
    asm("cvt.rna.tf32.f32 %0, %1;" : "=r"(r) : "f"(x));
    return r;
}

__device__ __forceinline__ void mma8(float* c,
                                     uint32_t a0, uint32_t a1, uint32_t a2, uint32_t a3,
                                     uint32_t b0, uint32_t b1) {
    asm volatile(
        "mma.sync.aligned.m16n8k8.row.col.f32.tf32.tf32.f32 "
        "{%0,%1,%2,%3},{%4,%5,%6,%7},{%8,%9},{%0,%1,%2,%3};\n"
        : "+f"(c[0]), "+f"(c[1]), "+f"(c[2]), "+f"(c[3])
        : "r"(a0), "r"(a1), "r"(a2), "r"(a3), "r"(b0), "r"(b1));
}

// Smem tiles: A 128 rows x 32 k (stride 36 words), B 32 k x 128 n (stride 136 words)
#define LDA 36
#define LDB 136

// Load one K-chunk (32) of A[128 x 32] and W[32 x 128] into smem (as tf32 bits).
// A is [M, 512] row-major, W is [512, 512] row-major.
__device__ __forceinline__ void load_tiles(const float* __restrict__ A,
                                           const float* __restrict__ W,
                                           int rowBase, int kt, int nBase,
                                           uint32_t* As, uint32_t* Bs, int tid) {
#pragma unroll
    for (int j = 0; j < 4; j++) {
        int pos = tid + j * 256;          // 0..1023 -> 128 rows x 8 float4
        int r  = pos >> 3;
        int kq = pos & 7;
        float4 v = *reinterpret_cast<const float4*>(A + (rowBase + r) * DIN + kt * 32 + kq * 4);
        uint32_t* dst = As + r * LDA + kq * 4;
        dst[0] = f2tf(v.x); dst[1] = f2tf(v.y); dst[2] = f2tf(v.z); dst[3] = f2tf(v.w);
    }
#pragma unroll
    for (int j = 0; j < 4; j++) {
        int pos = tid + j * 256;          // 0..1023 -> 32 k-rows x 32 float4
        int kr = pos >> 5;
        int nq = pos & 31;
        float4 v = *reinterpret_cast<const float4*>(W + (kt * 32 + kr) * DHID + nBase + nq * 4);
        uint32_t* dst = Bs + kr * LDB + nq * 4;
        dst[0] = f2tf(v.x); dst[1] = f2tf(v.y); dst[2] = f2tf(v.z); dst[3] = f2tf(v.w);
    }
}

// One K-chunk of MMAs for this warp's 32x64 tile. c[mt][nt][4].
__device__ __forceinline__ void compute_chunk(const uint32_t* As, const uint32_t* Bs,
                                              float c[2][8][4],
                                              int warpM, int warpN, int g, int tig) {
#pragma unroll
    for (int k8 = 0; k8 < 4; k8++) {
        int kk = k8 * 8;
        uint32_t a[2][4];
#pragma unroll
        for (int mt = 0; mt < 2; mt++) {
            int rb = warpM * 32 + mt * 16;
            a[mt][0] = As[(rb + g) * LDA + kk + tig];
            a[mt][1] = As[(rb + g + 8) * LDA + kk + tig];
            a[mt][2] = As[(rb + g) * LDA + kk + tig + 4];
            a[mt][3] = As[(rb + g + 8) * LDA + kk + tig + 4];
        }
        uint32_t b[8][2];
#pragma unroll
        for (int nt = 0; nt < 8; nt++) {
            int nb = warpN * 64 + nt * 8 + g;
            b[nt][0] = Bs[(kk + tig) * LDB + nb];
            b[nt][1] = Bs[(kk + tig + 4) * LDB + nb];
        }
#pragma unroll
        for (int mt = 0; mt < 2; mt++)
#pragma unroll
            for (int nt = 0; nt < 8; nt++)
                mma8(c[mt][nt], a[mt][0], a[mt][1], a[mt][2], a[mt][3], b[nt][0], b[nt][1]);
    }
}

// Kernel 1: h = neigh_vecs @ mlp_w; pooled = relu(max_over_32rows(h) + b)
// Grid: (DHID/128, (BATCH*NNEI)/128). Each warp owns exactly one pool group (32 rows).
__global__ void __launch_bounds__(256)
k_mlp_maxpool(const float* __restrict__ neigh,
              const float* __restrict__ mlp_w,
              const float* __restrict__ mlp_b) {
    __shared__ uint32_t As[128 * LDA];
    __shared__ uint32_t Bs[32 * LDB];

    int tid  = threadIdx.x;
    int warp = tid >> 5, lane = tid & 31;
    int g = lane >> 2, tig = lane & 3;
    int warpM = warp & 3, warpN = warp >> 2;   // 4 x 2

    int rowBase = blockIdx.y * 128;
    int nBase   = blockIdx.x * 128;

    float c[2][8][4];
#pragma unroll
    for (int mt = 0; mt < 2; mt++)
#pragma unroll
        for (int nt = 0; nt < 8; nt++)
#pragma unroll
            for (int i = 0; i < 4; i++) c[mt][nt][i] = 0.f;

    for (int kt = 0; kt < DIN / 32; kt++) {
        __syncthreads();
        load_tiles(neigh, mlp_w, rowBase, kt, nBase, As, Bs, tid);
        __syncthreads();
        compute_chunk(As, Bs, c, warpM, warpN, g, tig);
    }

    // Epilogue: max over the warp's 32 rows (one neighbor group), + bias, relu.
    int group = blockIdx.y * 4 + warpM;     // batch index
#pragma unroll
    for (int nt = 0; nt < 8; nt++) {
        // rows held by this thread for column pair (2*tig, 2*tig+1):
        // mt0: g, g+8 ; mt1: g+16, g+24
        float m0 = fmaxf(fmaxf(c[0][nt][0], c[0][nt][2]), fmaxf(c[1][nt][0], c[1][nt][2]));
        float m1 = fmaxf(fmaxf(c[0][nt][1], c[0][nt][3]), fmaxf(c[1][nt][1], c[1][nt][3]));
#pragma unroll
        for (int off = 4; off < 32; off <<= 1) {
            m0 = fmaxf(m0, __shfl_xor_sync(0xffffffffu, m0, off));
            m1 = fmaxf(m1, __shfl_xor_sync(0xffffffffu, m1, off));
        }
        if (g == 0) {
            int col = nBase + warpN * 64 + nt * 8 + 2 * tig;
            float b0 = mlp_b[col], b1 = mlp_b[col + 1];
            g_pooled[group * DHID + col]     = fmaxf(m0 + b0, 0.f);
            g_pooled[group * DHID + col + 1] = fmaxf(m1 + b1, 0.f);
        }
    }
}

// Kernel 2: out = relu(pooled @ neigh_w + self_vecs @ self_w)
// Grid: (DOUT/128, BATCH/128).
__global__ void __launch_bounds__(256)
k_out(const float* __restrict__ selfv,
      const float* __restrict__ neigh_w,
      const float* __restrict__ self_w,
      float* __restrict__ out) {
    __shared__ uint32_t As[128 * LDA];
    __shared__ uint32_t Bs[32 * LDB];

    int tid  = threadIdx.x;
    int warp = tid >> 5, lane = tid & 31;
    int g = lane >> 2, tig = lane & 3;
    int warpM = warp & 3, warpN = warp >> 2;

    int rowBase = blockIdx.y * 128;
    int nBase   = blockIdx.x * 128;

    float c[2][8][4];
#pragma unroll
    for (int mt = 0; mt < 2; mt++)
#pragma unroll
        for (int nt = 0; nt < 8; nt++)
#pragma unroll
            for (int i = 0; i < 4; i++) c[mt][nt][i] = 0.f;

    for (int phase = 0; phase < 2; phase++) {
        const float* A = phase ? selfv  : g_pooled;
        const float* W = phase ? self_w : neigh_w;
        for (int kt = 0; kt < DHID / 32; kt++) {
            __syncthreads();
            load_tiles(A, W, rowBase, kt, nBase, As, Bs, tid);
            __syncthreads();
            compute_chunk(As, Bs, c, warpM, warpN, g, tig);
        }
    }

    // Epilogue: relu, write float2 per fragment row
#pragma unroll
    for (int mt = 0; mt < 2; mt++) {
#pragma unroll
        for (int nt = 0; nt < 8; nt++) {
            int row = rowBase + warpM * 32 + mt * 16 + g;
            int col = nBase + warpN * 64 + nt * 8 + 2 * tig;
            float2 v0 = make_float2(fmaxf(c[mt][nt][0], 0.f), fmaxf(c[mt][nt][1], 0.f));
            float2 v1 = make_float2(fmaxf(c[mt][nt][2], 0.f), fmaxf(c[mt][nt][3], 0.f));
            *reinterpret_cast<float2*>(out + row * DOUT + col)       = v0;
            *reinterpret_cast<float2*>(out + (row + 8) * DOUT + col) = v1;
        }
    }
}

extern "C" void kernel_launch(void* const* d_in, const int* in_sizes, int n_in,
                              void* d_out, int out_size) {
    const float* selfv   = (const float*)d_in[0];  // [8192, 512]
    const float* neigh   = (const float*)d_in[1];  // [8192, 32, 512]
    const float* mlp_w   = (const float*)d_in[2];  // [512, 512]
    const float* mlp_b   = (const float*)d_in[3];  // [512]
    const float* neigh_w = (const float*)d_in[4];  // [512, 512]
    const float* self_w  = (const float*)d_in[5];  // [512, 512]
    float* out = (float*)d_out;                    // [8192, 512]

    dim3 grid1(DHID / 128, (BATCH * NNEI) / 128);  // (4, 2048)
    k_mlp_maxpool<<<grid1, 256>>>(neigh, mlp_w, mlp_b);

    dim3 grid2(DOUT / 128, BATCH / 128);           // (4, 64)
    k_out<<<grid2, 256>>>(selfv, neigh_w, self_w, out);
}